// round 8
// baseline (speedup 1.0000x reference)
#include <cuda_runtime.h>
#include <cstdint>

#define LROW     32768
#define NTHREADS 128
#define CHUNK    8
#define TILE     1024                 // NTHREADS * CHUNK
#define NTILES   32                   // LROW / TILE
#define OCC      8
#define CTAS     (148 * OCC)          // persistent
#define SF4      264                  // float4 slots per stage buffer

// XOR swizzle at float4 granularity: coalesced writes and stride-2-float4
// window reads are both 4-phase (crossbar minimum) in smem.
__device__ __forceinline__ int swz(int v) { return v ^ ((v >> 3) & 7); }

// ---- f32x2 packed helpers (sm_100+) ----
__device__ __forceinline__ uint64_t pack2(float lo, float hi) {
    uint64_t r; asm("mov.b64 %0, {%1, %2};" : "=l"(r) : "f"(lo), "f"(hi)); return r;
}
__device__ __forceinline__ uint64_t dup2(float v) { return pack2(v, v); }
__device__ __forceinline__ void unpack2(uint64_t v, float& lo, float& hi) {
    asm("mov.b64 {%0, %1}, %2;" : "=f"(lo), "=f"(hi) : "l"(v));
}
__device__ __forceinline__ uint64_t fma2(uint64_t a, uint64_t b, uint64_t c) {
    uint64_t d; asm("fma.rn.f32x2 %0, %1, %2, %3;" : "=l"(d) : "l"(a), "l"(b), "l"(c)); return d;
}
__device__ __forceinline__ uint64_t mul2(uint64_t a, uint64_t b) {
    uint64_t d; asm("mul.rn.f32x2 %0, %1, %2;" : "=l"(d) : "l"(a), "l"(b)); return d;
}

__device__ __forceinline__ void cp16(float4* s, const float4* g) {
    uint32_t sa = (uint32_t)__cvta_generic_to_shared(s);
    asm volatile("cp.async.cg.shared.global [%0], [%1], 16;" :: "r"(sa), "l"(g));
}

__device__ __forceinline__ float4 ldg_f4_clamped(const float* __restrict__ xr, int j0) {
    float t[4];
#pragma unroll
    for (int u = 0; u < 4; ++u) {
        int gi = j0 + u;
        gi = max(0, min(gi, LROW - 1));
        t[u] = __ldg(xr + gi);
    }
    return make_float4(t[0], t[1], t[2], t[3]);
}

// Fused up-2x (12-tap polyphase) -> LeakyReLU(0.1) -> down-2x, f32x2-packed.
// Persistent CTAs; async double-buffered smem staging via cp.async (interior
// tiles) so no registers are burned on the refill and no LDG scoreboard wait
// sits on the critical path. Edge tiles (2/32) use clamped LDG+STS.
__global__ __launch_bounds__(NTHREADS, OCC)
void aa_act_kernel(const float* __restrict__ x,
                   const float* __restrict__ upf,
                   const float* __restrict__ dnf,
                   float* __restrict__ out,
                   int total_tiles)
{
    __shared__ __align__(16) float4 sbuf[2][SF4];

    // Packed taps (uniform, once per CTA lifetime).
    uint64_t f2[6], dnp[6];
#pragma unroll
    for (int e = 0; e < 6; ++e)
        f2[e] = pack2(2.0f * __ldg(upf + 2 * e), 2.0f * __ldg(upf + 2 * e + 1));
#pragma unroll
    for (int m = 0; m < 6; ++m)
        dnp[m] = pack2(__ldg(dnf + 2 * m + 1), __ldg(dnf + 2 * m));
    const uint64_t c55 = dup2(0.55f), c45 = dup2(0.45f);

    const int tid = threadIdx.x;
    // Swizzled smem indices are tile-invariant.
    int rv[6];
#pragma unroll
    for (int k = 0; k < 6; ++k) rv[k] = swz(2 * tid + k);
    const int w0 = swz(tid), w1 = swz(tid + 128), w2 = swz(tid + 256);

    int tile = blockIdx.x;
    if (tile >= total_tiles) return;

    // Stage tile t_'s window x[o0-8 .. o0+TILE+7] into sbuf[b_].
    auto stage = [&](int b_, int t_) {
        const int tpos = t_ & (NTILES - 1);
        const int o0   = tpos * TILE;
        const float* xr = x + (size_t)(t_ >> 5) * LROW;
        if ((tpos != 0) & (tpos != NTILES - 1)) {
            const float4* p = (const float4*)(xr + (o0 - 8));   // 16B aligned
            cp16(&sbuf[b_][w0], p + tid);
            cp16(&sbuf[b_][w1], p + tid + 128);
            if (tid < 8) cp16(&sbuf[b_][w2], p + tid + 256);
            asm volatile("cp.async.commit_group;");
        } else {
            sbuf[b_][w0] = ldg_f4_clamped(xr, o0 - 8 + 4 * tid);
            sbuf[b_][w1] = ldg_f4_clamped(xr, o0 - 8 + 4 * (tid + 128));
            if (tid < 8) sbuf[b_][w2] = ldg_f4_clamped(xr, o0 - 8 + 4 * (tid + 256));
        }
    };

    stage(0, tile);                                   // prologue
    asm volatile("cp.async.wait_group 0;" ::: "memory");
    __syncthreads();

    int buf = 0;
    for (; tile < total_tiles; tile += CTAS) {
        // Kick off next tile's async refill into the other buffer.
        const int ntile = tile + CTAS;
        if (ntile < total_tiles) stage(buf ^ 1, ntile);

        const int row = tile >> 5;
        const int o   = (tile & (NTILES - 1)) * TILE + tid * CHUNK;

        // Window x[o-8 .. o+15] from swizzled smem -> lane-duplicated packs.
        uint64_t xx[24];
#pragma unroll
        for (int k = 0; k < 6; ++k) {
            float4 q = sbuf[buf][rv[k]];
            xx[4 * k + 0] = dup2(q.x); xx[4 * k + 1] = dup2(q.y);
            xx[4 * k + 2] = dup2(q.z); xx[4 * k + 3] = dup2(q.w);
        }

        // Up-sample + lrelu, packed.  EO[t] = (E[t], O[t]),
        //   E[t]==act[2*(o-2+t)], O[t]==act[2*(o-3+t)+1]; window xx[t+3 .. t+8].
        uint64_t EO[13];
#pragma unroll
        for (int t = 0; t < 13; ++t) {
            uint64_t v = mul2(f2[0], xx[t + 3]);
#pragma unroll
            for (int e = 1; e < 6; ++e)
                v = fma2(f2[e], xx[t + 3 + e], v);
            uint64_t av = v & 0x7FFFFFFF7FFFFFFFULL;      // packed |v|
            EO[t] = fma2(c45, av, mul2(c55, v));          // packed lrelu
        }

        // Row-edge act-index fixups (act index clamps to act[0] / act[2L-1]).
        if (o == 0) {
            float a0 = __uint_as_float((uint32_t)EO[2]);          // E[2]==act[0]
            uint64_t p = dup2(a0);
            EO[0] = p; EO[1] = p; EO[2] = p;
        }
        if (o == LROW - CHUNK) {
            float aL = __uint_as_float((uint32_t)(EO[10] >> 32)); // O[10]==act[2L-1]
            uint64_t p = dup2(aL);
            EO[10] = p; EO[11] = p; EO[12] = p;
        }

        // Downsample: out[o+q] = sum_m dn[2m]*O[q+m] + dn[2m+1]*E[q+m]
        float acc[CHUNK];
#pragma unroll
        for (int q = 0; q < CHUNK; ++q) {
            uint64_t a2 = mul2(dnp[0], EO[q]);
#pragma unroll
            for (int m = 1; m < 6; ++m)
                a2 = fma2(dnp[m], EO[q + m], a2);
            float lo, hi; unpack2(a2, lo, hi);
            acc[q] = lo + hi;
        }

        float4* op = (float4*)(out + (size_t)row * LROW + o);
        op[0] = make_float4(acc[0], acc[1], acc[2], acc[3]);
        op[1] = make_float4(acc[4], acc[5], acc[6], acc[7]);

        // Refill has had the whole compute stage to land; settle + swap.
        asm volatile("cp.async.wait_group 0;" ::: "memory");
        __syncthreads();
        buf ^= 1;
    }
}

extern "C" void kernel_launch(void* const* d_in, const int* in_sizes, int n_in,
                              void* d_out, int out_size)
{
    const float* x   = (const float*)d_in[0];
    const float* upf = (const float*)d_in[1];
    const float* dnf = (const float*)d_in[2];
    float* out = (float*)d_out;

    const int rows = in_sizes[0] / LROW;           // 8*128 = 1024
    const int total_tiles = rows * NTILES;         // 32768
    aa_act_kernel<<<CTAS, NTHREADS>>>(x, upf, dnf, out, total_tiles);
}

// round 9
// speedup vs baseline: 1.1587x; 1.1587x over previous
#include <cuda_runtime.h>
#include <cstdint>

#define LROW     32768
#define NTHREADS 64
#define CHUNK    8
#define TILE     512                  // NTHREADS * CHUNK
#define NTILES   64                   // LROW / TILE
#define OCC      16
#define CTAS     (148 * OCC)          // persistent
#define SVEC     132                  // (TILE+16)/4 float4 slots used
#define SF4      140                  // + swizzle margin

// XOR swizzle at float4 granularity: coalesced writes and stride-2-float4
// window reads are both 4-phase (crossbar minimum) in smem.
__device__ __forceinline__ int swz(int v) { return v ^ ((v >> 3) & 7); }

// ---- f32x2 packed helpers (sm_100+) ----
__device__ __forceinline__ uint64_t pack2(float lo, float hi) {
    uint64_t r; asm("mov.b64 %0, {%1, %2};" : "=l"(r) : "f"(lo), "f"(hi)); return r;
}
__device__ __forceinline__ uint64_t dup2(float v) { return pack2(v, v); }
__device__ __forceinline__ void unpack2(uint64_t v, float& lo, float& hi) {
    asm("mov.b64 {%0, %1}, %2;" : "=f"(lo), "=f"(hi) : "l"(v));
}
__device__ __forceinline__ uint64_t fma2(uint64_t a, uint64_t b, uint64_t c) {
    uint64_t d; asm("fma.rn.f32x2 %0, %1, %2, %3;" : "=l"(d) : "l"(a), "l"(b), "l"(c)); return d;
}
__device__ __forceinline__ uint64_t mul2(uint64_t a, uint64_t b) {
    uint64_t d; asm("mul.rn.f32x2 %0, %1, %2;" : "=l"(d) : "l"(a), "l"(b)); return d;
}

__device__ __forceinline__ float4 ldg_f4_clamped(const float* __restrict__ xr, int j0) {
    float t[4];
#pragma unroll
    for (int u = 0; u < 4; ++u) {
        int gi = j0 + u;
        gi = max(0, min(gi, LROW - 1));
        t[u] = __ldg(xr + gi);
    }
    return make_float4(t[0], t[1], t[2], t[3]);
}

// Fused up-2x (12-tap polyphase) -> LeakyReLU(0.1) -> down-2x, f32x2-packed.
// Persistent 64-thread CTAs (2 warps): small barrier-coupling set, 16 CTAs/SM.
// Double-buffered swizzled smem staging, LDG->regs before compute, STS after.
__global__ __launch_bounds__(NTHREADS, OCC)
void aa_act_kernel(const float* __restrict__ x,
                   const float* __restrict__ upf,
                   const float* __restrict__ dnf,
                   float* __restrict__ out,
                   int total_tiles)
{
    __shared__ __align__(16) float4 sbuf[2][SF4];

    // Packed taps (uniform, once per CTA lifetime).
    uint64_t f2[6], dnp[6];
#pragma unroll
    for (int e = 0; e < 6; ++e)
        f2[e] = pack2(2.0f * __ldg(upf + 2 * e), 2.0f * __ldg(upf + 2 * e + 1));
#pragma unroll
    for (int m = 0; m < 6; ++m)
        dnp[m] = pack2(__ldg(dnf + 2 * m + 1), __ldg(dnf + 2 * m));
    const uint64_t c55 = dup2(0.55f), c45 = dup2(0.45f);

    const int tid = threadIdx.x;
    // Swizzled smem indices are tile-invariant.
    int rv[6];
#pragma unroll
    for (int k = 0; k < 6; ++k) rv[k] = swz(2 * tid + k);
    const int w0 = swz(tid), w1 = swz(tid + 64), w2 = swz(tid + 128);

    int tile = blockIdx.x;
    if (tile >= total_tiles) return;

    // Stage tile t_'s window x[o0-8 .. o0+TILE+7] into registers (row-clamped).
    auto ldg_stage = [&](int t_, float4& a, float4& b, float4& c) {
        const int tpos = t_ & (NTILES - 1);
        const int o0   = tpos * TILE;
        const float* xr = x + (size_t)(t_ >> 6) * LROW;
        if ((tpos != 0) & (tpos != NTILES - 1)) {
            const float4* p = (const float4*)(xr + (o0 - 8));   // 16B aligned
            a = __ldg(p + tid);
            b = __ldg(p + tid + 64);
            if (tid < 4) c = __ldg(p + tid + 128);
        } else {
            a = ldg_f4_clamped(xr, o0 - 8 + 4 * tid);
            b = ldg_f4_clamped(xr, o0 - 8 + 4 * (tid + 64));
            if (tid < 4) c = ldg_f4_clamped(xr, o0 - 8 + 4 * (tid + 128));
        }
    };
    auto sts_stage = [&](int b_, const float4& a, const float4& bb, const float4& c) {
        sbuf[b_][w0] = a;
        sbuf[b_][w1] = bb;
        if (tid < 4) sbuf[b_][w2] = c;
    };

    {   // prologue: fill buffer 0
        float4 a, b, c;
        ldg_stage(tile, a, b, c);
        sts_stage(0, a, b, c);
    }
    __syncthreads();

    int buf = 0;
    for (; tile < total_tiles; tile += CTAS) {
        // Issue next tile's global loads first (latency hidden behind compute).
        const int ntile = tile + CTAS;
        const bool have_next = ntile < total_tiles;
        float4 na, nb, nc;
        if (have_next) ldg_stage(ntile, na, nb, nc);

        const int row = tile >> 6;
        const int o   = (tile & (NTILES - 1)) * TILE + tid * CHUNK;

        // Window x[o-8 .. o+15] from swizzled smem -> lane-duplicated packs.
        uint64_t xx[24];
#pragma unroll
        for (int k = 0; k < 6; ++k) {
            float4 q = sbuf[buf][rv[k]];
            xx[4 * k + 0] = dup2(q.x); xx[4 * k + 1] = dup2(q.y);
            xx[4 * k + 2] = dup2(q.z); xx[4 * k + 3] = dup2(q.w);
        }

        // Up-sample + lrelu, packed.  EO[t] = (E[t], O[t]),
        //   E[t]==act[2*(o-2+t)], O[t]==act[2*(o-3+t)+1]; window xx[t+3 .. t+8].
        uint64_t EO[13];
#pragma unroll
        for (int t = 0; t < 13; ++t) {
            uint64_t v = mul2(f2[0], xx[t + 3]);
#pragma unroll
            for (int e = 1; e < 6; ++e)
                v = fma2(f2[e], xx[t + 3 + e], v);
            uint64_t av = v & 0x7FFFFFFF7FFFFFFFULL;      // packed |v|
            EO[t] = fma2(c45, av, mul2(c55, v));          // packed lrelu
        }

        // Row-edge act-index fixups (act index clamps to act[0] / act[2L-1]).
        if (o == 0) {
            float a0 = __uint_as_float((uint32_t)EO[2]);          // E[2]==act[0]
            uint64_t p = dup2(a0);
            EO[0] = p; EO[1] = p; EO[2] = p;
        }
        if (o == LROW - CHUNK) {
            float aL = __uint_as_float((uint32_t)(EO[10] >> 32)); // O[10]==act[2L-1]
            uint64_t p = dup2(aL);
            EO[10] = p; EO[11] = p; EO[12] = p;
        }

        // Downsample: out[o+q] = sum_m dn[2m]*O[q+m] + dn[2m+1]*E[q+m]
        float acc[CHUNK];
#pragma unroll
        for (int q = 0; q < CHUNK; ++q) {
            uint64_t a2 = mul2(dnp[0], EO[q]);
#pragma unroll
            for (int m = 1; m < 6; ++m)
                a2 = fma2(dnp[m], EO[q + m], a2);
            float lo, hi; unpack2(a2, lo, hi);
            acc[q] = lo + hi;
        }

        float4* op = (float4*)(out + (size_t)row * LROW + o);
        op[0] = make_float4(acc[0], acc[1], acc[2], acc[3]);
        op[1] = make_float4(acc[4], acc[5], acc[6], acc[7]);

        // Park next tile's window into the other buffer, then one barrier.
        if (have_next) sts_stage(buf ^ 1, na, nb, nc);
        __syncthreads();
        buf ^= 1;
    }
}

extern "C" void kernel_launch(void* const* d_in, const int* in_sizes, int n_in,
                              void* d_out, int out_size)
{
    const float* x   = (const float*)d_in[0];
    const float* upf = (const float*)d_in[1];
    const float* dnf = (const float*)d_in[2];
    float* out = (float*)d_out;

    const int rows = in_sizes[0] / LROW;           // 8*128 = 1024
    const int total_tiles = rows * NTILES;         // 65536
    aa_act_kernel<<<CTAS, NTHREADS>>>(x, upf, dnf, out, total_tiles);
}

// round 10
// speedup vs baseline: 1.2044x; 1.0394x over previous
#include <cuda_runtime.h>
#include <cstdint>

#define LROW     32768
#define NTHREADS 64
#define CHUNK    8
#define TILE     512                  // NTHREADS * CHUNK
#define NTILES   64                   // LROW / TILE
#define OCC      16
#define CTAS     (148 * OCC)          // persistent
#define SF4      140                  // float4 slots per stage buffer

// Kaiser-sinc taps, computed offline in high precision for
// kaiser_sinc_filter1d(cutoff=0.25, half_width=0.3, ksize=12):
//   beta = 0.1102*(2.285*5*pi*1.2 + 7.95 - 8.7) = 4.6638001
//   filt = normalize(0.5 * kaiser(12,beta) * sinc(0.5*(n-5.5)))
// Symmetric: filt = [T0,T1,T2,T3,T4,T5,T5,T4,T3,T2,T1,T0].
#define T0 ( 0.00202895f)
#define T1 ( 0.00938947f)
#define T2 (-0.02554328f)
#define T3 (-0.05765736f)
#define T4 ( 0.12857258f)
#define T5 ( 0.44320973f)

// XOR swizzle at float4 granularity: coalesced writes and stride-2-float4
// window reads are both 4-phase (crossbar minimum) in smem.
__device__ __forceinline__ int swz(int v) { return v ^ ((v >> 3) & 7); }

__device__ __forceinline__ float4 ldg_f4_clamped(const float* __restrict__ xr, int j0) {
    float t[4];
#pragma unroll
    for (int u = 0; u < 4; ++u) {
        int gi = j0 + u;
        gi = max(0, min(gi, LROW - 1));
        t[u] = __ldg(xr + gi);
    }
    return make_float4(t[0], t[1], t[2], t[3]);
}

// Fused up-2x (12-tap polyphase) -> LeakyReLU(0.1) -> down-2x.
// SCALAR math with immediate taps: FFMA-imm issues at rt=1/SMSP (vs FFMA2's
// bank-limited rt=3), which round-9 measurement showed to be the wall.
// Persistent 64-thread CTAs, double-buffered swizzled smem staging.
__global__ __launch_bounds__(NTHREADS, OCC)
void aa_act_kernel(const float* __restrict__ x,
                   const float* __restrict__ upf,
                   const float* __restrict__ dnf,
                   float* __restrict__ out,
                   int total_tiles)
{
    __shared__ __align__(16) float4 sbuf[2][SF4];

    // Immediate tap tables (fully unrolled indexing -> literal operands).
    // fe[e] = 2*filt[2e], fo[e] = 2*filt[2e+1]; down taps = filt.
    const float FE[6] = {2*T0, 2*T2, 2*T4, 2*T5, 2*T3, 2*T1};
    const float FO[6] = {2*T1, 2*T3, 2*T5, 2*T4, 2*T2, 2*T0};
    const float DN[12] = {T0,T1,T2,T3,T4,T5,T5,T4,T3,T2,T1,T0};

    const int tid = threadIdx.x;
    int rv[6];
#pragma unroll
    for (int k = 0; k < 6; ++k) rv[k] = swz(2 * tid + k);
    const int w0 = swz(tid), w1 = swz(tid + 64), w2 = swz(tid + 128);

    int tile = blockIdx.x;
    if (tile >= total_tiles) return;

    // Stage tile t_'s window x[o0-8 .. o0+TILE+7] into registers (row-clamped).
    auto ldg_stage = [&](int t_, float4& a, float4& b, float4& c) {
        const int tpos = t_ & (NTILES - 1);
        const int o0   = tpos * TILE;
        const float* xr = x + (size_t)(t_ >> 6) * LROW;
        if ((tpos != 0) & (tpos != NTILES - 1)) {
            const float4* p = (const float4*)(xr + (o0 - 8));   // 16B aligned
            a = __ldg(p + tid);
            b = __ldg(p + tid + 64);
            if (tid < 4) c = __ldg(p + tid + 128);
        } else {
            a = ldg_f4_clamped(xr, o0 - 8 + 4 * tid);
            b = ldg_f4_clamped(xr, o0 - 8 + 4 * (tid + 64));
            if (tid < 4) c = ldg_f4_clamped(xr, o0 - 8 + 4 * (tid + 128));
        }
    };
    auto sts_stage = [&](int b_, const float4& a, const float4& bb, const float4& c) {
        sbuf[b_][w0] = a;
        sbuf[b_][w1] = bb;
        if (tid < 4) sbuf[b_][w2] = c;
    };

    {   // prologue: fill buffer 0
        float4 a, b, c;
        ldg_stage(tile, a, b, c);
        sts_stage(0, a, b, c);
    }
    __syncthreads();

    int buf = 0;
    for (; tile < total_tiles; tile += CTAS) {
        // Issue next tile's global loads first (latency hidden behind compute).
        const int ntile = tile + CTAS;
        const bool have_next = ntile < total_tiles;
        float4 na, nb, nc;
        if (have_next) ldg_stage(ntile, na, nb, nc);

        const int row = tile >> 6;
        const int o   = (tile & (NTILES - 1)) * TILE + tid * CHUNK;

        // Window x[o-8 .. o+15] from swizzled smem (xv[j] = x[o-8+j]).
        float xv[24];
#pragma unroll
        for (int k = 0; k < 6; ++k) {
            float4 q = sbuf[buf][rv[k]];
            xv[4 * k + 0] = q.x; xv[4 * k + 1] = q.y;
            xv[4 * k + 2] = q.z; xv[4 * k + 3] = q.w;
        }

        // Up-sample + lrelu, scalar FFMA-imm.  Slot t reads xv[t+3 .. t+8].
        //   E[t]==act[2*(o-2+t)], O[t]==act[2*(o-3+t)+1]
        //   lrelu(v) = 0.55*v + 0.45*|v|
        float E[13], O[13];
#pragma unroll
        for (int t = 0; t < 13; ++t) {
            float se = FE[0] * xv[t + 3];
            float so = FO[0] * xv[t + 3];
#pragma unroll
            for (int e = 1; e < 6; ++e) {
                se = fmaf(FE[e], xv[t + 3 + e], se);
                so = fmaf(FO[e], xv[t + 3 + e], so);
            }
            E[t] = fmaf(0.45f, fabsf(se), 0.55f * se);
            O[t] = fmaf(0.45f, fabsf(so), 0.55f * so);
        }

        // Row-edge act-index fixups (act index clamps to act[0] / act[2L-1]).
        if (o == 0) {
            float a0 = E[2];                  // act[0]
            E[0] = a0; E[1] = a0;
            O[0] = a0; O[1] = a0; O[2] = a0;
        }
        if (o == LROW - CHUNK) {
            float aL = O[10];                 // act[2L-1]
            O[11] = aL; O[12] = aL;
            E[10] = aL; E[11] = aL; E[12] = aL;
        }

        // Downsample: out[o+q] = sum_m DN[2m]*O[q+m] + DN[2m+1]*E[q+m]
        float acc[CHUNK];
#pragma unroll
        for (int q = 0; q < CHUNK; ++q) {
            float a = DN[0] * O[q];
            a = fmaf(DN[1], E[q], a);
#pragma unroll
            for (int m = 1; m < 6; ++m) {
                a = fmaf(DN[2 * m],     O[q + m], a);
                a = fmaf(DN[2 * m + 1], E[q + m], a);
            }
            acc[q] = a;
        }

        float4* op = (float4*)(out + (size_t)row * LROW + o);
        op[0] = make_float4(acc[0], acc[1], acc[2], acc[3]);
        op[1] = make_float4(acc[4], acc[5], acc[6], acc[7]);

        // Park next tile's window into the other buffer, then one barrier.
        if (have_next) sts_stage(buf ^ 1, na, nb, nc);
        __syncthreads();
        buf ^= 1;
    }
}

extern "C" void kernel_launch(void* const* d_in, const int* in_sizes, int n_in,
                              void* d_out, int out_size)
{
    const float* x   = (const float*)d_in[0];
    const float* upf = (const float*)d_in[1];
    const float* dnf = (const float*)d_in[2];
    float* out = (float*)d_out;

    const int rows = in_sizes[0] / LROW;           // 8*128 = 1024
    const int total_tiles = rows * NTILES;         // 65536
    aa_act_kernel<<<CTAS, NTHREADS>>>(x, upf, dnf, out, total_tiles);
}